// round 7
// baseline (speedup 1.0000x reference)
#include <cuda_runtime.h>
#include <cstdint>

// Problem constants (fixed shapes per reference setup_inputs)
constexpr int NN   = 50000;    // batch_size * num_nodes
constexpr int NE   = 800000;   // edges
constexpr int DIM  = 128;      // D_IN == D_OUT

constexpr int CHUNK   = 512;
constexpr int NCHUNKS = (NN + CHUNK - 1) / CHUNK;   // 98

// Scratch (device globals; no allocation)
__device__ int g_cnt[NN];          // per-row degree
__device__ int g_row_start[NN];    // CSR offsets
__device__ int g_cursor[NN];       // fill cursors
__device__ int g_chunk_sum[NCHUNKS];
__device__ int g_bucket[NE];       // source node per edge, bucketed by dest
__device__ __align__(16) float g_mean[(size_t)NN * DIM];
__device__ int g_is64;             // 1 if edge_index is int64, 0 if int32

__device__ __forceinline__ uint32_t f32_tf32(float f) {
    uint32_t r;
    asm("cvt.rna.tf32.f32 %0, %1;" : "=r"(r) : "f"(f));
    return r;
}
// m16n8k8 TF32 tensor-core MMA (baseline sm_80+ instruction; runs on sm_103)
__device__ __forceinline__ void mma_tf32(float* d, const uint4& a, const uint2& b) {
    asm volatile("mma.sync.aligned.m16n8k8.row.col.f32.tf32.tf32.f32 "
                 "{%0,%1,%2,%3},{%4,%5,%6,%7},{%8,%9},{%0,%1,%2,%3};"
                 : "+f"(d[0]), "+f"(d[1]), "+f"(d[2]), "+f"(d[3])
                 : "r"(a.x), "r"(a.y), "r"(a.z), "r"(a.w), "r"(b.x), "r"(b.y));
}

// ===========================================================================
// K1: zero degree counters + detect edge_index dtype.
// int64 data read as int64 -> all values in [0, NN); int32 data read as
// int64 packs two indices per word -> out of range immediately.
// ===========================================================================
__global__ void __launch_bounds__(256) init_kernel(const void* __restrict__ ei) {
    int i = blockIdx.x * blockDim.x + threadIdx.x;
    if (i < NN) g_cnt[i] = 0;
    if (i == 0) {
        const long long* p = (const long long*)ei;
        int ok = 1;
        for (int k = 0; k < 1024; k++) {
            long long v = p[k];
            if (v < 0 || v >= NN) { ok = 0; break; }
        }
        g_is64 = ok;
    }
}

// K2: histogram of destination rows
__global__ void __launch_bounds__(256) hist_kernel(const void* __restrict__ ei) {
    int e = blockIdx.x * blockDim.x + threadIdx.x;
    if (e >= NE) return;
    int r = g_is64 ? (int)((const long long*)ei)[e] : ((const int*)ei)[e];
    if ((unsigned)r < (unsigned)NN) atomicAdd(&g_cnt[r], 1);
}

// K3: per-chunk degree sums
__global__ void __launch_bounds__(256) chunk_reduce_kernel() {
    __shared__ int s[256];
    int blk = blockIdx.x, t = threadIdx.x;
    int base = blk * CHUNK, v = 0;
    if (base + t < NN) v += g_cnt[base + t];
    if (base + t + 256 < NN) v += g_cnt[base + t + 256];
    s[t] = v;
    __syncthreads();
    for (int off = 128; off > 0; off >>= 1) {
        if (t < off) s[t] += s[t + off];
        __syncthreads();
    }
    if (t == 0) g_chunk_sum[blk] = s[0];
}

// K4: row scan (fused chunk prefix: each block sums chunk_sum[0..blk-1])
__global__ void __launch_bounds__(512) row_scan_kernel() {
    __shared__ int s[CHUNK];
    __shared__ int sc[128];
    __shared__ int s_base;
    int blk = blockIdx.x, t = threadIdx.x;

    if (t < 128) sc[t] = (t < blk && t < NCHUNKS) ? g_chunk_sum[t] : 0;
    __syncthreads();
    if (t < 64) sc[t] += sc[t + 64];
    __syncthreads();
    if (t < 32) {
        int v = sc[t] + sc[t + 32];
        for (int off = 16; off > 0; off >>= 1) v += __shfl_down_sync(0xffffffffu, v, off);
        if (t == 0) s_base = v;
    }

    int i = blk * CHUNK + t;
    int v = (i < NN) ? g_cnt[i] : 0;
    s[t] = v;
    __syncthreads();
    for (int off = 1; off < CHUNK; off <<= 1) {
        int add = (t >= off) ? s[t - off] : 0;
        __syncthreads();
        s[t] += add;
        __syncthreads();
    }
    if (i < NN) {
        int start = s_base + s[t] - v;
        g_row_start[i] = start;
        g_cursor[i] = start;
    }
}

// K5: bucket fill — scatter source indices into CSR order
__global__ void __launch_bounds__(256) fill_kernel(const void* __restrict__ ei) {
    int e = blockIdx.x * blockDim.x + threadIdx.x;
    if (e >= NE) return;
    int r, c;
    if (g_is64) {
        const long long* p = (const long long*)ei;
        r = (int)p[e];
        c = (int)p[NE + e];
    } else {
        const int* p = (const int*)ei;
        r = p[e];
        c = p[NE + e];
    }
    if ((unsigned)r >= (unsigned)NN || (unsigned)c >= (unsigned)NN) return;
    int pos = atomicAdd(&g_cursor[r], 1);
    g_bucket[pos] = c;
}

// K6: aggregate — one warp per destination row, register accumulators
__global__ void __launch_bounds__(256) aggregate_kernel(const float* __restrict__ x) {
    int warp = (blockIdx.x * blockDim.x + threadIdx.x) >> 5;
    if (warp >= NN) return;
    int lane = threadIdx.x & 31;

    int base = g_row_start[warp];
    int deg  = g_cnt[warp];

    float4 acc = make_float4(0.f, 0.f, 0.f, 0.f);
    for (int i0 = 0; i0 < deg; i0 += 32) {
        int n = min(32, deg - i0);
        int c = (i0 + lane < deg) ? g_bucket[base + i0 + lane] : 0;
#pragma unroll 4
        for (int j = 0; j < n; j++) {
            int cj = __shfl_sync(0xffffffffu, c, j);
            float4 v = reinterpret_cast<const float4*>(x + (size_t)cj * DIM)[lane];
            acc.x += v.x; acc.y += v.y; acc.z += v.z; acc.w += v.w;
        }
    }
    float inv = 1.0f / fmaxf((float)deg, 1.0f);
    acc.x *= inv; acc.y *= inv; acc.z *= inv; acc.w *= inv;
    reinterpret_cast<float4*>(g_mean + (size_t)warp * DIM)[lane] = acc;
}

// ===========================================================================
// K7: tensor-core TF32 GEMM via mma.sync (m16n8k8).
// out[row][o] = mean[row] . W[o] + b[o].  Block: 256 thr (8 warps), tile
// 128(M)x128(N), K=128.  Warps: 4x2 grid, each 32(M)x64(N) = 2 mtiles x 8
// ntiles x 16 ksteps of HMMA.  Fragments are staged FRAGMENT-MAJOR in smem:
// each lane's A-frag is one contiguous uint4 (LDS.128), B-frag one uint2
// (LDS.64) -> conflict-free, minimal LDS issue in the hot loop.
//
// A-frag element map (m16k8, row.col):  a0=(g,kk) a1=(g+8,kk) a2=(g,kk+4)
//   a3=(g+8,kk+4), lane = g*4 + (kk&3).
// B-frag (k8n8 col-major = W[n][k]):    b0=(kk,nn) b1=(kk+4,nn),
//   lane = nn*4 + (kk&3).
// ===========================================================================
constexpr int SMEM_GEMM_BYTES = 131072;   // A frags 64KB + B frags 64KB

__global__ void __launch_bounds__(256) gemm_mma_kernel(const float* __restrict__ W,
                                                       const float* __restrict__ bias,
                                                       float* __restrict__ out) {
    extern __shared__ uint32_t smem[];    // [0,16384): A frags, [16384,32768): B frags
    const int tid  = threadIdx.x;
    const int lane = tid & 31;
    const int wid  = tid >> 5;
    const int wm   = wid & 3;             // M warp: rows [wm*32, +32)
    const int wn   = wid >> 2;            // N warp: cols [wn*64, +64)
    const int row0 = blockIdx.x * 128;

    // ---- Stage A (mean tile) into fragment-major layout, tf32-converted ----
#pragma unroll
    for (int it = 0; it < 16; it++) {
        int idx = it * 256 + tid;         // 4096 float4 groups
        int row = idx >> 5;
        int k   = (idx & 31) * 4;
        int mt = row >> 4, r = row & 15, g = r & 7;
        int ks = k >> 3;
        int slot = (((k & 7) >= 4) ? 2 : 0) + ((r >= 8) ? 1 : 0);
        int grow = row0 + row;
        float4 v = (grow < NN)
                 ? *reinterpret_cast<const float4*>(g_mean + (size_t)grow * DIM + k)
                 : make_float4(0.f, 0.f, 0.f, 0.f);
        uint32_t* p = smem + ((mt * 16 + ks) * 32 + g * 4) * 4 + slot;
        p[0]  = f32_tf32(v.x);
        p[4]  = f32_tf32(v.y);
        p[8]  = f32_tf32(v.z);
        p[12] = f32_tf32(v.w);
    }
    // ---- Stage B (W) into fragment-major layout ----
#pragma unroll
    for (int it = 0; it < 16; it++) {
        int idx = it * 256 + tid;
        int n = idx >> 5;
        int k = (idx & 31) * 4;
        int nt = n >> 3, nn = n & 7;
        int ks = k >> 3;
        int slot = ((k & 7) >= 4) ? 1 : 0;
        float4 v = *reinterpret_cast<const float4*>(W + (size_t)n * DIM + k);
        uint32_t* p = smem + 16384 + ((nt * 16 + ks) * 32 + nn * 4) * 2 + slot;
        p[0] = f32_tf32(v.x);
        p[2] = f32_tf32(v.y);
        p[4] = f32_tf32(v.z);
        p[6] = f32_tf32(v.w);
    }
    __syncthreads();

    // ---- HMMA mainloop ----
    float d[2][8][4];
#pragma unroll
    for (int mi = 0; mi < 2; mi++)
#pragma unroll
        for (int ni = 0; ni < 8; ni++)
#pragma unroll
            for (int q = 0; q < 4; q++) d[mi][ni][q] = 0.f;

    const uint32_t* Af = smem;
    const uint32_t* Bf = smem + 16384;
#pragma unroll
    for (int ks = 0; ks < 16; ks++) {
        uint4 a0 = *reinterpret_cast<const uint4*>(&Af[(((wm * 2 + 0) * 16 + ks) * 32 + lane) * 4]);
        uint4 a1 = *reinterpret_cast<const uint4*>(&Af[(((wm * 2 + 1) * 16 + ks) * 32 + lane) * 4]);
#pragma unroll
        for (int ni = 0; ni < 8; ni++) {
            uint2 b = *reinterpret_cast<const uint2*>(&Bf[(((wn * 8 + ni) * 16 + ks) * 32 + lane) * 2]);
            mma_tf32(d[0][ni], a0, b);
            mma_tf32(d[1][ni], a1, b);
        }
    }

    // ---- Epilogue: +bias, float2 stores ----
    int qr = lane >> 2, qc = (lane & 3) * 2;
#pragma unroll
    for (int ni = 0; ni < 8; ni++) {
        int col = wn * 64 + ni * 8 + qc;
        float2 bb = *reinterpret_cast<const float2*>(bias + col);
#pragma unroll
        for (int mi = 0; mi < 2; mi++) {
            int row = row0 + wm * 32 + mi * 16 + qr;
            if (row < NN) {
                float2 o = make_float2(d[mi][ni][0] + bb.x, d[mi][ni][1] + bb.y);
                *reinterpret_cast<float2*>(out + (size_t)row * DIM + col) = o;
            }
            if (row + 8 < NN) {
                float2 o = make_float2(d[mi][ni][2] + bb.x, d[mi][ni][3] + bb.y);
                *reinterpret_cast<float2*>(out + (size_t)(row + 8) * DIM + col) = o;
            }
        }
    }
}

// ===========================================================================
// Launch chain. Inputs resolved by element count.
// ===========================================================================
extern "C" void kernel_launch(void* const* d_in, const int* in_sizes, int n_in,
                              void* d_out, int out_size) {
    const float* x = nullptr;
    const void*  ei = nullptr;
    const float* W = nullptr;
    const float* b = nullptr;

    for (int i = 0; i < n_in; i++) {
        switch (in_sizes[i]) {
            case NN * DIM:    if (!x)  x  = (const float*)d_in[i]; break;
            case 2 * NE:      if (!ei) ei = d_in[i];               break;
            case DIM * DIM:   if (!W)  W  = (const float*)d_in[i]; break;
            case DIM:         if (!b)  b  = (const float*)d_in[i]; break;
            default: break;
        }
    }
    float* out = (float*)d_out;

    cudaFuncSetAttribute(gemm_mma_kernel,
                         cudaFuncAttributeMaxDynamicSharedMemorySize, SMEM_GEMM_BYTES);

    init_kernel<<<(NN + 255) / 256, 256>>>(ei);
    hist_kernel<<<(NE + 255) / 256, 256>>>(ei);
    chunk_reduce_kernel<<<NCHUNKS, 256>>>();
    row_scan_kernel<<<NCHUNKS, 512>>>();
    fill_kernel<<<(NE + 255) / 256, 256>>>(ei);
    aggregate_kernel<<<(NN * 32 + 255) / 256, 256>>>(x);
    gemm_mma_kernel<<<(NN + 127) / 128, 256, SMEM_GEMM_BYTES>>>(W, b, out);
}

// round 12
// speedup vs baseline: 1.7886x; 1.7886x over previous
#include <cuda_runtime.h>
#include <cstdint>

// Problem constants (fixed shapes per reference setup_inputs)
constexpr int NN   = 50000;    // batch_size * num_nodes
constexpr int NE   = 800000;   // edges
constexpr int DIM  = 128;      // D_IN == D_OUT

constexpr int CHUNK   = 512;
constexpr int NCHUNKS = (NN + CHUNK - 1) / CHUNK;   // 98

// Scratch (device globals; no allocation)
__device__ int g_cnt[NN];          // per-row degree
__device__ int g_row_start[NN];    // CSR offsets
__device__ int g_cursor[NN];       // fill cursors
__device__ int g_chunk_sum[NCHUNKS];
__device__ int g_bucket[NE];       // source node per edge, bucketed by dest
__device__ __align__(16) float g_mean[(size_t)NN * DIM];
__device__ int g_is64;             // 1 if edge_index is int64, 0 if int32

__device__ __forceinline__ uint32_t f32_tf32(float f) {
    uint32_t r;
    asm("cvt.rna.tf32.f32 %0, %1;" : "=r"(r) : "f"(f));
    return r;
}
// m16n8k8 TF32 tensor-core MMA (baseline sm_80+ instruction; runs on sm_103)
__device__ __forceinline__ void mma_tf32(float* d, const uint4& a, const uint2& b) {
    asm volatile("mma.sync.aligned.m16n8k8.row.col.f32.tf32.tf32.f32 "
                 "{%0,%1,%2,%3},{%4,%5,%6,%7},{%8,%9},{%0,%1,%2,%3};"
                 : "+f"(d[0]), "+f"(d[1]), "+f"(d[2]), "+f"(d[3])
                 : "r"(a.x), "r"(a.y), "r"(a.z), "r"(a.w), "r"(b.x), "r"(b.y));
}

// ===========================================================================
// K1: zero degree counters + detect edge_index dtype.
// ===========================================================================
__global__ void __launch_bounds__(256) init_kernel(const void* __restrict__ ei) {
    int i = blockIdx.x * blockDim.x + threadIdx.x;
    if (i < NN) g_cnt[i] = 0;
    if (i == 0) {
        const long long* p = (const long long*)ei;
        int ok = 1;
        for (int k = 0; k < 1024; k++) {
            long long v = p[k];
            if (v < 0 || v >= NN) { ok = 0; break; }
        }
        g_is64 = ok;
    }
}

// K2: histogram of destination rows
__global__ void __launch_bounds__(256) hist_kernel(const void* __restrict__ ei) {
    int e = blockIdx.x * blockDim.x + threadIdx.x;
    if (e >= NE) return;
    int r = g_is64 ? (int)((const long long*)ei)[e] : ((const int*)ei)[e];
    if ((unsigned)r < (unsigned)NN) atomicAdd(&g_cnt[r], 1);
}

// K3: per-chunk degree sums
__global__ void __launch_bounds__(256) chunk_reduce_kernel() {
    __shared__ int s[256];
    int blk = blockIdx.x, t = threadIdx.x;
    int base = blk * CHUNK, v = 0;
    if (base + t < NN) v += g_cnt[base + t];
    if (base + t + 256 < NN) v += g_cnt[base + t + 256];
    s[t] = v;
    __syncthreads();
    for (int off = 128; off > 0; off >>= 1) {
        if (t < off) s[t] += s[t + off];
        __syncthreads();
    }
    if (t == 0) g_chunk_sum[blk] = s[0];
}

// K4: row scan (fused chunk prefix: each block sums chunk_sum[0..blk-1])
__global__ void __launch_bounds__(512) row_scan_kernel() {
    __shared__ int s[CHUNK];
    __shared__ int sc[128];
    __shared__ int s_base;
    int blk = blockIdx.x, t = threadIdx.x;

    if (t < 128) sc[t] = (t < blk && t < NCHUNKS) ? g_chunk_sum[t] : 0;
    __syncthreads();
    if (t < 64) sc[t] += sc[t + 64];
    __syncthreads();
    if (t < 32) {
        int v = sc[t] + sc[t + 32];
        for (int off = 16; off > 0; off >>= 1) v += __shfl_down_sync(0xffffffffu, v, off);
        if (t == 0) s_base = v;
    }

    int i = blk * CHUNK + t;
    int v = (i < NN) ? g_cnt[i] : 0;
    s[t] = v;
    __syncthreads();
    for (int off = 1; off < CHUNK; off <<= 1) {
        int add = (t >= off) ? s[t - off] : 0;
        __syncthreads();
        s[t] += add;
        __syncthreads();
    }
    if (i < NN) {
        int start = s_base + s[t] - v;
        g_row_start[i] = start;
        g_cursor[i] = start;
    }
}

// K5: bucket fill — scatter source indices into CSR order
__global__ void __launch_bounds__(256) fill_kernel(const void* __restrict__ ei) {
    int e = blockIdx.x * blockDim.x + threadIdx.x;
    if (e >= NE) return;
    int r, c;
    if (g_is64) {
        const long long* p = (const long long*)ei;
        r = (int)p[e];
        c = (int)p[NE + e];
    } else {
        const int* p = (const int*)ei;
        r = p[e];
        c = p[NE + e];
    }
    if ((unsigned)r >= (unsigned)NN || (unsigned)c >= (unsigned)NN) return;
    int pos = atomicAdd(&g_cursor[r], 1);
    g_bucket[pos] = c;
}

// K6: aggregate — one warp per destination row, register accumulators
__global__ void __launch_bounds__(256) aggregate_kernel(const float* __restrict__ x) {
    int warp = (blockIdx.x * blockDim.x + threadIdx.x) >> 5;
    if (warp >= NN) return;
    int lane = threadIdx.x & 31;

    int base = g_row_start[warp];
    int deg  = g_cnt[warp];

    float4 acc = make_float4(0.f, 0.f, 0.f, 0.f);
    for (int i0 = 0; i0 < deg; i0 += 32) {
        int n = min(32, deg - i0);
        int c = (i0 + lane < deg) ? g_bucket[base + i0 + lane] : 0;
#pragma unroll 4
        for (int j = 0; j < n; j++) {
            int cj = __shfl_sync(0xffffffffu, c, j);
            float4 v = reinterpret_cast<const float4*>(x + (size_t)cj * DIM)[lane];
            acc.x += v.x; acc.y += v.y; acc.z += v.z; acc.w += v.w;
        }
    }
    float inv = 1.0f / fmaxf((float)deg, 1.0f);
    acc.x *= inv; acc.y *= inv; acc.z *= inv; acc.w *= inv;
    reinterpret_cast<float4*>(g_mean + (size_t)warp * DIM)[lane] = acc;
}

// ===========================================================================
// K7: tensor-core TF32 GEMM via mma.sync (m16n8k8) — v2.
// Row-major smem tiles with 68-word row stride (68 mod 32 = 4): fragment
// LDS.32 addresses map to bank g*4+kk -> all 32 lanes distinct, conflict-
// free; STS.128 staging phases conflict-free too. K split into 2 chunks of
// 64 -> smem 69.6 KB -> 3 CTAs/SM -> 391 blocks in ONE wave.
// Block: 256 thr (8 warps 4Mx2N), tile 128(M)x128(N); warp tile 32x64.
// ===========================================================================
constexpr int TS = 68;                       // smem row stride in words
constexpr int SMEM_GEMM_BYTES = 2 * 128 * TS * 4;   // 69632

__global__ void __launch_bounds__(256) gemm_mma_kernel(const float* __restrict__ W,
                                                       const float* __restrict__ bias,
                                                       float* __restrict__ out) {
    extern __shared__ uint32_t smem[];
    uint32_t* As = smem;               // [128][TS]
    uint32_t* Bs = smem + 128 * TS;    // [128][TS]
    const int tid  = threadIdx.x;
    const int lane = tid & 31;
    const int wid  = tid >> 5;
    const int wm   = wid & 3;          // M warp: rows [wm*32, +32)
    const int wn   = wid >> 2;         // N warp: cols [wn*64, +64)
    const int row0 = blockIdx.x * 128;
    const int g    = lane >> 2;        // fragment group row 0..7
    const int kk   = lane & 3;         // fragment k offset 0..3

    float d[2][8][4];
#pragma unroll
    for (int mi = 0; mi < 2; mi++)
#pragma unroll
        for (int ni = 0; ni < 8; ni++)
#pragma unroll
            for (int q = 0; q < 4; q++) d[mi][ni][q] = 0.f;

    for (int kc = 0; kc < 2; kc++) {
        const int k0 = kc * 64;
        // ---- Stage A (mean tile rows, tf32) : 128x64, 2048 float4 ----
#pragma unroll
        for (int it = 0; it < 8; it++) {
            int idx = it * 256 + tid;
            int row = idx >> 4;            // 16 float4 per row
            int k   = (idx & 15) * 4;
            int grow = row0 + row;
            float4 v = (grow < NN)
                     ? *reinterpret_cast<const float4*>(g_mean + (size_t)grow * DIM + k0 + k)
                     : make_float4(0.f, 0.f, 0.f, 0.f);
            uint4 t = make_uint4(f32_tf32(v.x), f32_tf32(v.y), f32_tf32(v.z), f32_tf32(v.w));
            *reinterpret_cast<uint4*>(&As[row * TS + k]) = t;
        }
        // ---- Stage B (W rows, tf32) ----
#pragma unroll
        for (int it = 0; it < 8; it++) {
            int idx = it * 256 + tid;
            int n = idx >> 4;
            int k = (idx & 15) * 4;
            float4 v = *reinterpret_cast<const float4*>(W + (size_t)n * DIM + k0 + k);
            uint4 t = make_uint4(f32_tf32(v.x), f32_tf32(v.y), f32_tf32(v.z), f32_tf32(v.w));
            *reinterpret_cast<uint4*>(&Bs[n * TS + k]) = t;
        }
        __syncthreads();

        // ---- HMMA over 8 k-steps of this chunk ----
#pragma unroll
        for (int ks = 0; ks < 8; ks++) {
            const int c = ks * 8 + kk;
            uint4 a[2];
#pragma unroll
            for (int mi = 0; mi < 2; mi++) {
                int r = wm * 32 + mi * 16 + g;
                a[mi].x = As[r * TS + c];
                a[mi].y = As[(r + 8) * TS + c];
                a[mi].z = As[r * TS + c + 4];
                a[mi].w = As[(r + 8) * TS + c + 4];
            }
#pragma unroll
            for (int ni = 0; ni < 8; ni++) {
                int n = wn * 64 + ni * 8 + g;
                uint2 b;
                b.x = Bs[n * TS + c];
                b.y = Bs[n * TS + c + 4];
                mma_tf32(d[0][ni], a[0], b);
                mma_tf32(d[1][ni], a[1], b);
            }
        }
        __syncthreads();
    }

    // ---- Epilogue: +bias, float2 stores (32B sector-aligned groups) ----
    int qr = lane >> 2, qc = (lane & 3) * 2;
#pragma unroll
    for (int ni = 0; ni < 8; ni++) {
        int col = wn * 64 + ni * 8 + qc;
        float2 bb = *reinterpret_cast<const float2*>(bias + col);
#pragma unroll
        for (int mi = 0; mi < 2; mi++) {
            int row = row0 + wm * 32 + mi * 16 + qr;
            if (row < NN) {
                float2 o = make_float2(d[mi][ni][0] + bb.x, d[mi][ni][1] + bb.y);
                *reinterpret_cast<float2*>(out + (size_t)row * DIM + col) = o;
            }
            if (row + 8 < NN) {
                float2 o = make_float2(d[mi][ni][2] + bb.x, d[mi][ni][3] + bb.y);
                *reinterpret_cast<float2*>(out + (size_t)(row + 8) * DIM + col) = o;
            }
        }
    }
}

// ===========================================================================
// Launch chain. Inputs resolved by element count.
// ===========================================================================
extern "C" void kernel_launch(void* const* d_in, const int* in_sizes, int n_in,
                              void* d_out, int out_size) {
    const float* x = nullptr;
    const void*  ei = nullptr;
    const float* W = nullptr;
    const float* b = nullptr;

    for (int i = 0; i < n_in; i++) {
        switch (in_sizes[i]) {
            case NN * DIM:    if (!x)  x  = (const float*)d_in[i]; break;
            case 2 * NE:      if (!ei) ei = d_in[i];               break;
            case DIM * DIM:   if (!W)  W  = (const float*)d_in[i]; break;
            case DIM:         if (!b)  b  = (const float*)d_in[i]; break;
            default: break;
        }
    }
    float* out = (float*)d_out;

    cudaFuncSetAttribute(gemm_mma_kernel,
                         cudaFuncAttributeMaxDynamicSharedMemorySize, SMEM_GEMM_BYTES);

    init_kernel<<<(NN + 255) / 256, 256>>>(ei);
    hist_kernel<<<(NE + 255) / 256, 256>>>(ei);
    chunk_reduce_kernel<<<NCHUNKS, 256>>>();
    row_scan_kernel<<<NCHUNKS, 512>>>();
    fill_kernel<<<(NE + 255) / 256, 256>>>(ei);
    aggregate_kernel<<<(NN * 32 + 255) / 256, 256>>>(x);
    gemm_mma_kernel<<<(NN + 127) / 128, 256, SMEM_GEMM_BYTES>>>(W, b, out);
}